// round 1
// baseline (speedup 1.0000x reference)
#include <cuda_runtime.h>

#define NROWS 8192
#define HID   256
#define BM    64
#define BN    64
#define NTHREADS 256

// scratch for projected Q, K, V (8 MB each; __device__ globals are the
// sanctioned scratch mechanism under the allocation guards)
__device__ float g_q[NROWS * HID];
__device__ float g_k[NROWS * HID];
__device__ float g_v[NROWS * HID];

typedef unsigned long long u64;

__device__ __forceinline__ u64 pk2(float x, float y) {
    u64 r; asm("mov.b64 %0, {%1,%2};" : "=l"(r) : "f"(x), "f"(y)); return r;
}
__device__ __forceinline__ void upk2(u64 v, float& x, float& y) {
    asm("mov.b64 {%0,%1}, %2;" : "=f"(x), "=f"(y) : "l"(v));
}
// packed fp32x2 FMA (sm_100+): doubles fp32 FMA throughput vs FFMA-3reg
__device__ __forceinline__ u64 fma2(u64 a, u64 b, u64 c) {
    u64 d; asm("fma.rn.f32x2 %0, %1, %2, %3;" : "=l"(d) : "l"(a), "l"(b), "l"(c)); return d;
}
__device__ __forceinline__ float sigmoidf_(float x) {
    return __frcp_rn(1.0f + __expf(-x));
}

// ---------------------------------------------------------------------------
// out[row, col] = X[row,:] . W[col,:] + bias[col]    (X: [8192,256], W: [256,256])
// 64x64 tile per CTA, 256 threads, 4 rows x 4 cols per thread (as 2 f32x2 pairs)
// ---------------------------------------------------------------------------
__global__ __launch_bounds__(NTHREADS)
void linear_kernel(const float* __restrict__ X, const float* __restrict__ W,
                   const float* __restrict__ bias, float* __restrict__ out)
{
    __shared__ float sX[32 * 64];   // [k][m]
    __shared__ float sW[32 * 64];   // [k][n]
    const int tid  = threadIdx.x;
    const int row0 = blockIdx.x * 64;
    const int col0 = blockIdx.y * 64;
    const int m0   = (tid >> 4) << 2;   // 0..60
    const int ac2  = (tid & 15) << 1;   // 0..30 (col pair base; 2nd pair at +32)
    const int lm   = tid & 63;
    const int lk   = (tid >> 6) << 3;

    u64 acc[4][2];
#pragma unroll
    for (int r = 0; r < 4; r++) { acc[r][0] = 0ull; acc[r][1] = 0ull; }

    const float* Xp = X + (row0 + lm) * HID + lk;
    const float* Wp = W + (col0 + lm) * HID + lk;

    for (int k0 = 0; k0 < HID; k0 += 32) {
        float4 xa = *(const float4*)(Xp + k0);
        float4 xb = *(const float4*)(Xp + k0 + 4);
        float4 wa = *(const float4*)(Wp + k0);
        float4 wb = *(const float4*)(Wp + k0 + 4);
        sX[(lk + 0) * 64 + lm] = xa.x; sX[(lk + 1) * 64 + lm] = xa.y;
        sX[(lk + 2) * 64 + lm] = xa.z; sX[(lk + 3) * 64 + lm] = xa.w;
        sX[(lk + 4) * 64 + lm] = xb.x; sX[(lk + 5) * 64 + lm] = xb.y;
        sX[(lk + 6) * 64 + lm] = xb.z; sX[(lk + 7) * 64 + lm] = xb.w;
        sW[(lk + 0) * 64 + lm] = wa.x; sW[(lk + 1) * 64 + lm] = wa.y;
        sW[(lk + 2) * 64 + lm] = wa.z; sW[(lk + 3) * 64 + lm] = wa.w;
        sW[(lk + 4) * 64 + lm] = wb.x; sW[(lk + 5) * 64 + lm] = wb.y;
        sW[(lk + 6) * 64 + lm] = wb.z; sW[(lk + 7) * 64 + lm] = wb.w;
        __syncthreads();
#pragma unroll
        for (int kk = 0; kk < 32; kk++) {
            float4 q = *(const float4*)(sX + kk * 64 + m0);
            u64 b0 = *(const u64*)(sW + kk * 64 + ac2);
            u64 b1 = *(const u64*)(sW + kk * 64 + ac2 + 32);
            u64 a;
            a = pk2(q.x, q.x); acc[0][0] = fma2(a, b0, acc[0][0]); acc[0][1] = fma2(a, b1, acc[0][1]);
            a = pk2(q.y, q.y); acc[1][0] = fma2(a, b0, acc[1][0]); acc[1][1] = fma2(a, b1, acc[1][1]);
            a = pk2(q.z, q.z); acc[2][0] = fma2(a, b0, acc[2][0]); acc[2][1] = fma2(a, b1, acc[2][1]);
            a = pk2(q.w, q.w); acc[3][0] = fma2(a, b0, acc[3][0]); acc[3][1] = fma2(a, b1, acc[3][1]);
        }
        __syncthreads();
    }
    const int c0 = col0 + ac2;
    const float b0 = bias[c0],      b1 = bias[c0 + 1];
    const float b2 = bias[c0 + 32], b3 = bias[c0 + 33];
#pragma unroll
    for (int r = 0; r < 4; r++) {
        float x, y;
        upk2(acc[r][0], x, y);
        *(float2*)(out + (row0 + m0 + r) * HID + c0) = make_float2(x + b0, y + b1);
        upk2(acc[r][1], x, y);
        *(float2*)(out + (row0 + m0 + r) * HID + c0 + 32) = make_float2(x + b2, y + b3);
    }
}

// ---------------------------------------------------------------------------
// Fused sigmoid attention: out[i,:] = sum_j sigmoid(q_i . k_j) * v_j
// CTA = 64 Q rows; loop over 8192 K/V rows in chunks of 64.
//   stage A: S = Q Kt (Q,K k-major in smem, f32x2 packed over col pairs)
//   sigmoid -> P stored transposed + column-duplicated: sP[j][2m]=sP[j][2m+1]=P[m][j]
//   stage B: acc(64x256) += P V, 8 rows x 8 cols per thread (all f32x2)
// smem: Q 64KB + K 64KB + V 64KB + P 33KB = 230400 B (dynamic, opt-in)
// ---------------------------------------------------------------------------
#define SQ_OFF 0
#define SK_OFF 16384
#define SV_OFF 32768
#define SP_OFF 49152
#define SP_STRIDE 132            // 128 used + pad; 132*4 % 16 == 0 for LDS.128
#define SMEM_FLOATS (49152 + BN * SP_STRIDE)   // 57600 floats = 230400 bytes

__global__ __launch_bounds__(NTHREADS)
void attn_kernel(float* __restrict__ out)
{
    extern __shared__ float smem[];
    float* sQ = smem + SQ_OFF;    // [k][m] 256x64
    float* sK = smem + SK_OFF;    // [k][j] 256x64
    float* sV = smem + SV_OFF;    // [j][c] 64x256
    float* sP = smem + SP_OFF;    // [j][2m dup] 64x132

    const int tid  = threadIdx.x;
    const int row0 = blockIdx.x * BM;
    const int lm   = tid & 63;
    const int lkb  = tid >> 6;    // 0..3

    // load Q tile transposed into sQ[k*64+m]
    {
        const float* gq = g_q + (row0 + lm) * HID;
#pragma unroll
        for (int kb = 0; kb < 4; kb++) {
            int k0 = (lkb + kb * 4) * 16;
#pragma unroll
            for (int j = 0; j < 4; j++) {
                float4 v = *(const float4*)(gq + k0 + j * 4);
                sQ[(k0 + j * 4 + 0) * 64 + lm] = v.x;
                sQ[(k0 + j * 4 + 1) * 64 + lm] = v.y;
                sQ[(k0 + j * 4 + 2) * 64 + lm] = v.z;
                sQ[(k0 + j * 4 + 3) * 64 + lm] = v.w;
            }
        }
    }

    const int ar0  = (tid >> 4) << 2;   // stage A rows
    const int ac2  = (tid & 15) << 1;   // stage A col-pair base
    const int warp = tid >> 5;
    const int lane = tid & 31;
    const int br2  = warp << 4;         // 2 * (warp*8): stage B row base in dup'd P
    const int cl2  = lane << 1;         // stage B col-pair base

    u64 accB[8][4];
#pragma unroll
    for (int r = 0; r < 8; r++)
#pragma unroll
        for (int i = 0; i < 4; i++) accB[r][i] = 0ull;

    for (int j0 = 0; j0 < NROWS; j0 += BN) {
        __syncthreads();   // previous iteration done with sK/sV/sP (covers sQ on iter 0)

        // load K chunk transposed
        {
            const float* gk = g_k + (j0 + lm) * HID;
#pragma unroll
            for (int kb = 0; kb < 4; kb++) {
                int k0 = (lkb + kb * 4) * 16;
#pragma unroll
                for (int j = 0; j < 4; j++) {
                    float4 v = *(const float4*)(gk + k0 + j * 4);
                    sK[(k0 + j * 4 + 0) * 64 + lm] = v.x;
                    sK[(k0 + j * 4 + 1) * 64 + lm] = v.y;
                    sK[(k0 + j * 4 + 2) * 64 + lm] = v.z;
                    sK[(k0 + j * 4 + 3) * 64 + lm] = v.w;
                }
            }
        }
        // load V chunk (row-major, coalesced float4)
        {
#pragma unroll
            for (int i = 0; i < 16; i++) {
                int f = tid + i * 256;          // float4 index within 64x256 tile
                int r = f >> 6;
                int c = (f & 63) << 2;
                *(float4*)(sV + r * 256 + c) = *(const float4*)(g_v + (j0 + r) * HID + c);
            }
        }
        __syncthreads();

        // ---- stage A: S[64][64] = Q . Kt over k=256 ----
        u64 a00 = 0, a01 = 0, a10 = 0, a11 = 0, a20 = 0, a21 = 0, a30 = 0, a31 = 0;
        const float* q_ptr = sQ + ar0;
        const float* k_ptr = sK + ac2;
#pragma unroll 8
        for (int kk = 0; kk < HID; kk++) {
            float4 q = *(const float4*)(q_ptr + kk * 64);
            u64 b0 = *(const u64*)(k_ptr + kk * 64);
            u64 b1 = *(const u64*)(k_ptr + kk * 64 + 32);
            u64 a;
            a = pk2(q.x, q.x); a00 = fma2(a, b0, a00); a01 = fma2(a, b1, a01);
            a = pk2(q.y, q.y); a10 = fma2(a, b0, a10); a11 = fma2(a, b1, a11);
            a = pk2(q.z, q.z); a20 = fma2(a, b0, a20); a21 = fma2(a, b1, a21);
            a = pk2(q.w, q.w); a30 = fma2(a, b0, a30); a31 = fma2(a, b1, a31);
        }
        // sigmoid + transposed duplicated store
        {
            float xs[4][4];
            upk2(a00, xs[0][0], xs[0][1]); upk2(a01, xs[0][2], xs[0][3]);
            upk2(a10, xs[1][0], xs[1][1]); upk2(a11, xs[1][2], xs[1][3]);
            upk2(a20, xs[2][0], xs[2][1]); upk2(a21, xs[2][2], xs[2][3]);
            upk2(a30, xs[3][0], xs[3][1]); upk2(a31, xs[3][2], xs[3][3]);
            const int ccol[4] = {ac2, ac2 + 1, ac2 + 32, ac2 + 33};
#pragma unroll
            for (int r = 0; r < 4; r++) {
#pragma unroll
                for (int c = 0; c < 4; c++) {
                    float s = sigmoidf_(xs[r][c]);
                    *(u64*)(sP + ccol[c] * SP_STRIDE + ((ar0 + r) << 1)) = pk2(s, s);
                }
            }
        }
        __syncthreads();

        // ---- stage B: acc += P V ----
        const float* p_base = sP + br2;
        const float* v_base = sV + cl2;
#pragma unroll 2
        for (int jj = 0; jj < BN; jj++) {
            const float* pr = p_base + jj * SP_STRIDE;
            ulonglong2 p01 = *(const ulonglong2*)(pr);       // (P[r0],P[r0]),(P[r1],P[r1])
            ulonglong2 p23 = *(const ulonglong2*)(pr + 4);
            ulonglong2 p45 = *(const ulonglong2*)(pr + 8);
            ulonglong2 p67 = *(const ulonglong2*)(pr + 12);
            const float* vr = v_base + jj * 256;
            u64 v0 = *(const u64*)(vr);
            u64 v1 = *(const u64*)(vr + 64);
            u64 v2 = *(const u64*)(vr + 128);
            u64 v3 = *(const u64*)(vr + 192);
            accB[0][0] = fma2(p01.x, v0, accB[0][0]); accB[0][1] = fma2(p01.x, v1, accB[0][1]);
            accB[0][2] = fma2(p01.x, v2, accB[0][2]); accB[0][3] = fma2(p01.x, v3, accB[0][3]);
            accB[1][0] = fma2(p01.y, v0, accB[1][0]); accB[1][1] = fma2(p01.y, v1, accB[1][1]);
            accB[1][2] = fma2(p01.y, v2, accB[1][2]); accB[1][3] = fma2(p01.y, v3, accB[1][3]);
            accB[2][0] = fma2(p23.x, v0, accB[2][0]); accB[2][1] = fma2(p23.x, v1, accB[2][1]);
            accB[2][2] = fma2(p23.x, v2, accB[2][2]); accB[2][3] = fma2(p23.x, v3, accB[2][3]);
            accB[3][0] = fma2(p23.y, v0, accB[3][0]); accB[3][1] = fma2(p23.y, v1, accB[3][1]);
            accB[3][2] = fma2(p23.y, v2, accB[3][2]); accB[3][3] = fma2(p23.y, v3, accB[3][3]);
            accB[4][0] = fma2(p45.x, v0, accB[4][0]); accB[4][1] = fma2(p45.x, v1, accB[4][1]);
            accB[4][2] = fma2(p45.x, v2, accB[4][2]); accB[4][3] = fma2(p45.x, v3, accB[4][3]);
            accB[5][0] = fma2(p45.y, v0, accB[5][0]); accB[5][1] = fma2(p45.y, v1, accB[5][1]);
            accB[5][2] = fma2(p45.y, v2, accB[5][2]); accB[5][3] = fma2(p45.y, v3, accB[5][3]);
            accB[6][0] = fma2(p67.x, v0, accB[6][0]); accB[6][1] = fma2(p67.x, v1, accB[6][1]);
            accB[6][2] = fma2(p67.x, v2, accB[6][2]); accB[6][3] = fma2(p67.x, v3, accB[6][3]);
            accB[7][0] = fma2(p67.y, v0, accB[7][0]); accB[7][1] = fma2(p67.y, v1, accB[7][1]);
            accB[7][2] = fma2(p67.y, v2, accB[7][2]); accB[7][3] = fma2(p67.y, v3, accB[7][3]);
        }
    }

    // epilogue: write 64x256 output tile
#pragma unroll
    for (int r = 0; r < 8; r++) {
        float* orow = out + (row0 + (warp << 3) + r) * HID + cl2;
        float x, y;
#pragma unroll
        for (int i = 0; i < 4; i++) {
            upk2(accB[r][i], x, y);
            *(float2*)(orow + i * 64) = make_float2(x, y);
        }
    }
}

// ---------------------------------------------------------------------------
extern "C" void kernel_launch(void* const* d_in, const int* in_sizes, int n_in,
                              void* d_out, int out_size)
{
    const float* query = (const float*)d_in[0];
    const float* key_  = (const float*)d_in[1];
    const float* value = (const float*)d_in[2];
    const float* Wq    = (const float*)d_in[3];
    const float* bq    = (const float*)d_in[4];
    const float* Wk    = (const float*)d_in[5];
    const float* bk    = (const float*)d_in[6];
    const float* Wv    = (const float*)d_in[7];
    const float* bv    = (const float*)d_in[8];
    float* out = (float*)d_out;
    (void)in_sizes; (void)n_in; (void)out_size;

    float *dq, *dk, *dv;
    cudaGetSymbolAddress((void**)&dq, g_q);
    cudaGetSymbolAddress((void**)&dk, g_k);
    cudaGetSymbolAddress((void**)&dv, g_v);

    dim3 lgrid(NROWS / 64, HID / 64);
    linear_kernel<<<lgrid, NTHREADS>>>(query, Wq, bq, dq);
    linear_kernel<<<lgrid, NTHREADS>>>(key_,  Wk, bk, dk);
    linear_kernel<<<lgrid, NTHREADS>>>(value, Wv, bv, dv);

    int smem_bytes = SMEM_FLOATS * (int)sizeof(float);   // 230400 <= 232448 opt-in max
    cudaFuncSetAttribute(attn_kernel, cudaFuncAttributeMaxDynamicSharedMemorySize, smem_bytes);
    attn_kernel<<<NROWS / BM, NTHREADS, smem_bytes>>>(out);
}